// round 6
// baseline (speedup 1.0000x reference)
#include <cuda_runtime.h>
#include <math.h>
#include <float.h>

#define Bb   512
#define Cc   2048
#define HWn  48
#define NAT  51
#define HIDn 128
#define S1   16    // K-splits for pooled @ W1^T  (K=2048 -> 128/split)
#define NTIL 16    // channel tiles in gate kernel (2048/128)

// Scratch (static __device__ globals: allocation-free rule)
__device__ float g_pooled[Bb * Cc];            // max_hw(body*A*face), 0 for non-front rows
__device__ float g_bmean [Bb * Cc];            // mean_hw(body)
__device__ float g_hp    [S1 * Bb * HIDn];     // split-K partials of pooled @ W1^T
__device__ float g_h     [Bb * HIDn];          // relu(sum hp + b1)
__device__ float g_zp    [NTIL * NAT * Bb];    // per-n-tile partials of gap @ Wl^T, [nt][j][b]

// ---------------------------------------------------------------------------
// K1: streaming pass, float4 loads. Each warp: 8 contiguous channels =
// 96 float4 = 3 fully-active coalesced iterations. Reduction via smem
// (4 threads/channel) + 2 shfl levels. (Unchanged from R5 — proven.)
// ---------------------------------------------------------------------------
__global__ void __launch_bounds__(256) k1_reduce(
    const float* __restrict__ body, const float* __restrict__ face,
    const float* __restrict__ Af,   const int*   __restrict__ pose)
{
    __shared__ float sm_s[8][96];
    __shared__ float sm_m[8][96];
    __shared__ float out_s[64], out_m[64];
    int tid  = threadIdx.x;
    int wid  = tid >> 5;
    int lane = tid & 31;
    int blk_ch = blockIdx.x * 64;
    int b = blk_ch >> 11;
    bool front = (pose[b] == 1);
    int wbase = blk_ch + wid * 8;

    const float4* bp4 = (const float4*)body + (size_t)wbase * 12;
    float4 bv[3];
    #pragma unroll
    for (int k = 0; k < 3; k++)
        bv[k] = bp4[k * 32 + lane];
    if (front) {
        const float4* fp4 = (const float4*)face + (size_t)wbase * 12;
        const float4* ap4 = (const float4*)Af   + (size_t)(wbase & (Cc - 1)) * 12;
        #pragma unroll
        for (int k = 0; k < 3; k++) {
            float4 fv = fp4[k * 32 + lane];
            float4 av = ap4[k * 32 + lane];
            float m01 = fmaxf(bv[k].x * av.x * fv.x, bv[k].y * av.y * fv.y);
            float m23 = fmaxf(bv[k].z * av.z * fv.z, bv[k].w * av.w * fv.w);
            sm_m[wid][k * 32 + lane] = fmaxf(m01, m23);
        }
    }
    #pragma unroll
    for (int k = 0; k < 3; k++)
        sm_s[wid][k * 32 + lane] = (bv[k].x + bv[k].y) + (bv[k].z + bv[k].w);
    __syncthreads();

    {
        int chl = tid >> 2;
        int w2  = chl >> 3;
        int off = (chl & 7) * 12 + (tid & 3) * 3;
        float ss = sm_s[w2][off] + sm_s[w2][off + 1] + sm_s[w2][off + 2];
        ss += __shfl_xor_sync(0xffffffffu, ss, 1);
        ss += __shfl_xor_sync(0xffffffffu, ss, 2);
        float mm = 0.f;
        if (front) {
            mm = fmaxf(fmaxf(sm_m[w2][off], sm_m[w2][off + 1]), sm_m[w2][off + 2]);
            mm = fmaxf(mm, __shfl_xor_sync(0xffffffffu, mm, 1));
            mm = fmaxf(mm, __shfl_xor_sync(0xffffffffu, mm, 2));
        }
        if ((tid & 3) == 0) {
            out_s[chl] = ss * (1.0f / 48.0f);
            out_m[chl] = mm;
        }
    }
    __syncthreads();
    if (tid < 64)        g_bmean [blk_ch + tid]      = out_s[tid];
    else if (tid < 128)  g_pooled[blk_ch + tid - 64] = out_m[tid - 64];
}

// ---------------------------------------------------------------------------
// GEMM1 split-K: hp[s] = pooled[512, k-chunk] @ W1[128, k-chunk]^T
// ---------------------------------------------------------------------------
__global__ void __launch_bounds__(256) gemm1(
    const float* __restrict__ A, const float* __restrict__ Bw,
    float* __restrict__ hp)
{
    __shared__ float As[16][68];
    __shared__ float Bs[16][68];
    int s  = blockIdx.z;
    int m0 = blockIdx.x * 64;
    int n0 = blockIdx.y * 64;
    int k0 = s * (Cc / S1);
    int tid = threadIdx.x;
    int tx = tid & 15, ty = tid >> 4;
    int r  = tid >> 2;
    int q  = (tid & 3) * 4;
    float acc[4][4] = {};

    const float* ap = &A [(size_t)(m0 + r) * Cc + k0 + q];
    const float* bp = &Bw[(size_t)(n0 + r) * Cc + k0 + q];
    float4 areg = *(const float4*)ap;
    float4 breg = *(const float4*)bp;

    #pragma unroll
    for (int kt = 0; kt < Cc / S1; kt += 16) {
        As[q+0][r] = areg.x; As[q+1][r] = areg.y; As[q+2][r] = areg.z; As[q+3][r] = areg.w;
        Bs[q+0][r] = breg.x; Bs[q+1][r] = breg.y; Bs[q+2][r] = breg.z; Bs[q+3][r] = breg.w;
        __syncthreads();
        if (kt + 16 < Cc / S1) {
            areg = *(const float4*)(ap + kt + 16);
            breg = *(const float4*)(bp + kt + 16);
        }
        #pragma unroll
        for (int kk = 0; kk < 16; kk++) {
            float4 a4 = *(const float4*)&As[kk][ty * 4];
            float4 b4 = *(const float4*)&Bs[kk][tx * 4];
            float a[4]  = {a4.x, a4.y, a4.z, a4.w};
            float bb[4] = {b4.x, b4.y, b4.z, b4.w};
            #pragma unroll
            for (int i = 0; i < 4; i++)
                #pragma unroll
                for (int j = 0; j < 4; j++)
                    acc[i][j] = fmaf(a[i], bb[j], acc[i][j]);
        }
        __syncthreads();
    }
    #pragma unroll
    for (int i = 0; i < 4; i++) {
        int m = m0 + ty * 4 + i;
        #pragma unroll
        for (int j = 0; j < 4; j++) {
            int n = n0 + tx * 4 + j;
            hp[((size_t)s * Bb + m) * HIDn + n] = acc[i][j];
        }
    }
}

// ---------------------------------------------------------------------------
// hreduce: h = relu(sum_s hp[s] + b1)
// ---------------------------------------------------------------------------
__global__ void __launch_bounds__(256) hreduce(const float* __restrict__ b1v)
{
    int i4 = blockIdx.x * 256 + threadIdx.x;
    float4 v = *(const float4*)&g_hp[(size_t)i4 * 4];
    #pragma unroll
    for (int s = 1; s < S1; s++) {
        float4 t = *(const float4*)&g_hp[(size_t)s * (Bb * HIDn) + (size_t)i4 * 4];
        v.x += t.x; v.y += t.y; v.z += t.z; v.w += t.w;
    }
    float4 bv = *(const float4*)&b1v[(i4 & 31) * 4];
    v.x = fmaxf(v.x + bv.x, 0.f);
    v.y = fmaxf(v.y + bv.y, 0.f);
    v.z = fmaxf(v.z + bv.z, 0.f);
    v.w = fmaxf(v.w + bv.w, 0.f);
    *(float4*)&g_h[(size_t)i4 * 4] = v;
}

// ---------------------------------------------------------------------------
// GATE v3: 64(batch)x128(chan) tile, 256 threads, 4x8 micro-tile,
// double-buffered smem (1 barrier per k-tile). Columns per thread:
// {tx*4..+3} and {64+tx*4..+3} -> each B LDS.128 is conflict-optimal.
// gap = bmean + front*sigmoid(h @ W2^T + b2); fused z-partial epilogue
// in two 64-channel passes; block sums both -> zp[nt=blockIdx.y].
// ---------------------------------------------------------------------------
__global__ void __launch_bounds__(256) gemm_gate(
    const float* __restrict__ W2,  const float* __restrict__ b2v,
    const float* __restrict__ Wl,  const int*   __restrict__ pose)
{
    // mainloop: A double-buf [2][16][68], B double-buf [2][16][136] = 26112 B
    // epilogue: gapT[64][68] + WlT[64][68] = 34816 B  (union)
    __shared__ __align__(16) float smemBuf[64 * 68 + 64 * 68];   // 34816 B
    float* Abuf = smemBuf;                    // [2][16][68]
    float* Bbuf = smemBuf + 2 * 16 * 68;      // [2][16][136]
    float (*gapT)[68] = (float(*)[68]) smemBuf;            // [64][68]
    float (*WlT)[68]  = (float(*)[68])(smemBuf + 64 * 68); // [64][68]

    int m0 = blockIdx.x * 64;
    int n0 = blockIdx.y * 128;
    int tid = threadIdx.x;
    int tx = tid & 15, ty = tid >> 4;
    int ra = tid >> 2, qa = (tid & 3) * 4;    // A loader: row 0..63, 4 k's
    int rb = tid >> 1, qb = (tid & 1) * 8;    // B loader: row 0..127, 8 k's
    float acc[4][8] = {};

    const float* ap = &g_h[(size_t)(m0 + ra) * HIDn + qa];
    const float* bp = &W2 [(size_t)(n0 + rb) * HIDn + qb];

    float4 areg  = *(const float4*)ap;
    float4 breg0 = *(const float4*)bp;
    float4 breg1 = *(const float4*)(bp + 4);
    {   // store tile 0 into buffer 0
        float* Ad = Abuf;
        float* Bd = Bbuf;
        Ad[(qa+0)*68 + ra] = areg.x;  Ad[(qa+1)*68 + ra] = areg.y;
        Ad[(qa+2)*68 + ra] = areg.z;  Ad[(qa+3)*68 + ra] = areg.w;
        Bd[(qb+0)*136 + rb] = breg0.x; Bd[(qb+1)*136 + rb] = breg0.y;
        Bd[(qb+2)*136 + rb] = breg0.z; Bd[(qb+3)*136 + rb] = breg0.w;
        Bd[(qb+4)*136 + rb] = breg1.x; Bd[(qb+5)*136 + rb] = breg1.y;
        Bd[(qb+6)*136 + rb] = breg1.z; Bd[(qb+7)*136 + rb] = breg1.w;
    }
    __syncthreads();

    #pragma unroll
    for (int kt = 0; kt < 8; kt++) {                 // 8 k-tiles of 16
        int cur = kt & 1;
        if (kt < 7) {
            areg  = *(const float4*)(ap + (kt + 1) * 16);
            breg0 = *(const float4*)(bp + (kt + 1) * 16);
            breg1 = *(const float4*)(bp + (kt + 1) * 16 + 4);
        }
        const float* Ac = Abuf + cur * (16 * 68);
        const float* Bc = Bbuf + cur * (16 * 136);
        #pragma unroll
        for (int kk = 0; kk < 16; kk++) {
            float4 a4  = *(const float4*)&Ac[kk * 68  + ty * 4];
            float4 b40 = *(const float4*)&Bc[kk * 136 + tx * 4];
            float4 b41 = *(const float4*)&Bc[kk * 136 + 64 + tx * 4];
            float a[4]  = {a4.x, a4.y, a4.z, a4.w};
            float bb[8] = {b40.x, b40.y, b40.z, b40.w,
                           b41.x, b41.y, b41.z, b41.w};
            #pragma unroll
            for (int i = 0; i < 4; i++)
                #pragma unroll
                for (int j = 0; j < 8; j++)
                    acc[i][j] = fmaf(a[i], bb[j], acc[i][j]);
        }
        if (kt < 7) {
            int nxt = cur ^ 1;
            float* Ad = Abuf + nxt * (16 * 68);
            float* Bd = Bbuf + nxt * (16 * 136);
            Ad[(qa+0)*68 + ra] = areg.x;  Ad[(qa+1)*68 + ra] = areg.y;
            Ad[(qa+2)*68 + ra] = areg.z;  Ad[(qa+3)*68 + ra] = areg.w;
            Bd[(qb+0)*136 + rb] = breg0.x; Bd[(qb+1)*136 + rb] = breg0.y;
            Bd[(qb+2)*136 + rb] = breg0.z; Bd[(qb+3)*136 + rb] = breg0.w;
            Bd[(qb+4)*136 + rb] = breg1.x; Bd[(qb+5)*136 + rb] = breg1.y;
            Bd[(qb+6)*136 + rb] = breg1.z; Bd[(qb+7)*136 + rb] = breg1.w;
        }
        __syncthreads();
    }
    // last iteration ended with __syncthreads(): smem free for epilogue.

    float fr[4];
    #pragma unroll
    for (int i = 0; i < 4; i++)
        fr[i] = (pose[m0 + ty * 4 + i] == 1) ? 1.0f : 0.0f;

    float acc2[4][4] = {};
    #pragma unroll
    for (int p = 0; p < 2; p++) {
        // gap for channels [n0+64p, n0+64p+64) -> gapT (chan-major)
        #pragma unroll
        for (int i = 0; i < 4; i++) {
            int m = m0 + ty * 4 + i;
            #pragma unroll
            for (int jj = 0; jj < 4; jj++) {
                int n = n0 + 64 * p + tx * 4 + jj;
                float v = acc[i][p * 4 + jj] + b2v[n];
                float g = 1.0f / (1.0f + expf(-v));
                gapT[tx * 4 + jj][ty * 4 + i] =
                    g_bmean[(size_t)m * Cc + n] + fr[i] * g;
            }
        }
        // Wl chunk (51 attrs x 64 channels) transposed + zero-padded
        for (int idx = tid; idx < 64 * 68; idx += 256) {
            int cc = idx / 68, j = idx - cc * 68;
            WlT[cc][j] = (j < NAT) ? Wl[(size_t)j * Cc + n0 + 64 * p + cc] : 0.f;
        }
        __syncthreads();
        #pragma unroll 8
        for (int cc = 0; cc < 64; cc++) {
            float4 g4 = *(const float4*)&gapT[cc][ty * 4];
            float4 w4 = *(const float4*)&WlT [cc][tx * 4];
            float gg[4] = {g4.x, g4.y, g4.z, g4.w};
            float ww[4] = {w4.x, w4.y, w4.z, w4.w};
            #pragma unroll
            for (int i = 0; i < 4; i++)
                #pragma unroll
                for (int j = 0; j < 4; j++)
                    acc2[i][j] = fmaf(gg[i], ww[j], acc2[i][j]);
        }
        __syncthreads();
    }

    int nt = blockIdx.y;
    #pragma unroll
    for (int j = 0; j < 4; j++) {
        int attr = tx * 4 + j;
        if (attr < NAT) {
            #pragma unroll
            for (int i = 0; i < 4; i++) {
                int m = m0 + ty * 4 + i;
                g_zp[((size_t)nt * NAT + attr) * Bb + m] = acc2[i][j];
            }
        }
    }
}

// ---------------------------------------------------------------------------
// BN: one block per attribute (NTIL=16 partials).
// ---------------------------------------------------------------------------
__global__ void __launch_bounds__(256) bn_kernel(
    const float* __restrict__ blv, const float* __restrict__ gam,
    const float* __restrict__ bet, float* __restrict__ out)
{
    __shared__ float zbuf[Bb];
    __shared__ float red[256];
    int j   = blockIdx.x;
    int tid = threadIdx.x;
    float bias = blv[j];
    float lsum = 0.f;
    for (int b = tid; b < Bb; b += 256) {
        float z = bias;
        #pragma unroll
        for (int nt = 0; nt < NTIL; nt++)
            z += g_zp[((size_t)nt * NAT + j) * Bb + b];
        zbuf[b] = z;
        lsum += z;
    }
    red[tid] = lsum;
    __syncthreads();
    for (int off = 128; off; off >>= 1) {
        if (tid < off) red[tid] += red[tid + off];
        __syncthreads();
    }
    float mu = red[0] * (1.0f / Bb);
    __syncthreads();
    float lvar = 0.f;
    for (int b = tid; b < Bb; b += 256) {
        float d = zbuf[b] - mu;
        lvar += d * d;
    }
    red[tid] = lvar;
    __syncthreads();
    for (int off = 128; off; off >>= 1) {
        if (tid < off) red[tid] += red[tid + off];
        __syncthreads();
    }
    float inv = rsqrtf(red[0] * (1.0f / Bb) + 1e-5f);
    float ga = gam[j], be = bet[j];
    for (int b = tid; b < Bb; b += 256)
        out[(size_t)b * NAT + j] = ga * (zbuf[b] - mu) * inv + be;
}

// ---------------------------------------------------------------------------
extern "C" void kernel_launch(void* const* d_in, const int* in_sizes, int n_in,
                              void* d_out, int out_size)
{
    const float* body = (const float*)d_in[0];
    const float* face = (const float*)d_in[1];
    const int*   pose = (const int*)  d_in[2];
    const float* Af   = (const float*)d_in[3];
    const float* W1   = (const float*)d_in[4];
    const float* b1v  = (const float*)d_in[5];
    const float* W2   = (const float*)d_in[6];
    const float* b2v  = (const float*)d_in[7];
    const float* Wl   = (const float*)d_in[8];
    const float* blv  = (const float*)d_in[9];
    const float* gam  = (const float*)d_in[10];
    const float* bet  = (const float*)d_in[11];
    float* out = (float*)d_out;

    float *pooled_p, *hp_p;
    cudaGetSymbolAddress((void**)&pooled_p, g_pooled);
    cudaGetSymbolAddress((void**)&hp_p,     g_hp);

    // 1) streaming reduce: pooled max + body mean
    k1_reduce<<<(Bb * Cc) / 64, 256>>>(body, face, Af, pose);
    // 2) hp[s] = pooled @ W1^T  (16-way split-K partials)
    gemm1<<<dim3(Bb / 64, HIDn / 64, S1), 256>>>(pooled_p, W1, hp_p);
    // 3) h = relu(sum hp + b1)
    hreduce<<<(Bb * HIDn / 4) / 256, 256>>>(b1v);
    // 4) gate GEMM v3 (64x128 tiles, double-buffered) + fused z-partials
    gemm_gate<<<dim3(Bb / 64, NTIL), 256>>>(W2, b2v, Wl, pose);
    // 5) reduce partials + bias + batchnorm
    bn_kernel<<<NAT, 256>>>(blv, gam, bet, out);
}

// round 7
// speedup vs baseline: 1.0064x; 1.0064x over previous
#include <cuda_runtime.h>
#include <math.h>
#include <float.h>

#define Bb   512
#define Cc   2048
#define HWn  48
#define NAT  51
#define HIDn 128
#define S1   16    // K-splits for pooled @ W1^T  (K=2048 -> 128/split)
#define NTIL 32    // channel tiles in gate kernel (2048/64)

// Scratch (static __device__ globals: allocation-free rule)
__device__ float g_pooled[Bb * Cc];            // max_hw(body*A*face), 0 for non-front rows
__device__ float g_bmean [Bb * Cc];            // mean_hw(body)
__device__ float g_hp    [S1 * Bb * HIDn];     // split-K partials of pooled @ W1^T
__device__ float g_h     [Bb * HIDn];          // relu(sum hp + b1)
__device__ float g_zp    [NTIL * NAT * Bb];    // per-n-tile partials of gap @ Wl^T, [nt][j][b]

// ---------------------------------------------------------------------------
// K1: streaming pass, float4 loads (unchanged — proven, near HBM bound).
// ---------------------------------------------------------------------------
__global__ void __launch_bounds__(256) k1_reduce(
    const float* __restrict__ body, const float* __restrict__ face,
    const float* __restrict__ Af,   const int*   __restrict__ pose)
{
    __shared__ float sm_s[8][96];
    __shared__ float sm_m[8][96];
    __shared__ float out_s[64], out_m[64];
    int tid  = threadIdx.x;
    int wid  = tid >> 5;
    int lane = tid & 31;
    int blk_ch = blockIdx.x * 64;
    int b = blk_ch >> 11;
    bool front = (pose[b] == 1);
    int wbase = blk_ch + wid * 8;

    const float4* bp4 = (const float4*)body + (size_t)wbase * 12;
    float4 bv[3];
    #pragma unroll
    for (int k = 0; k < 3; k++)
        bv[k] = bp4[k * 32 + lane];
    if (front) {
        const float4* fp4 = (const float4*)face + (size_t)wbase * 12;
        const float4* ap4 = (const float4*)Af   + (size_t)(wbase & (Cc - 1)) * 12;
        #pragma unroll
        for (int k = 0; k < 3; k++) {
            float4 fv = fp4[k * 32 + lane];
            float4 av = ap4[k * 32 + lane];
            float m01 = fmaxf(bv[k].x * av.x * fv.x, bv[k].y * av.y * fv.y);
            float m23 = fmaxf(bv[k].z * av.z * fv.z, bv[k].w * av.w * fv.w);
            sm_m[wid][k * 32 + lane] = fmaxf(m01, m23);
        }
    }
    #pragma unroll
    for (int k = 0; k < 3; k++)
        sm_s[wid][k * 32 + lane] = (bv[k].x + bv[k].y) + (bv[k].z + bv[k].w);
    __syncthreads();

    {
        int chl = tid >> 2;
        int w2  = chl >> 3;
        int off = (chl & 7) * 12 + (tid & 3) * 3;
        float ss = sm_s[w2][off] + sm_s[w2][off + 1] + sm_s[w2][off + 2];
        ss += __shfl_xor_sync(0xffffffffu, ss, 1);
        ss += __shfl_xor_sync(0xffffffffu, ss, 2);
        float mm = 0.f;
        if (front) {
            mm = fmaxf(fmaxf(sm_m[w2][off], sm_m[w2][off + 1]), sm_m[w2][off + 2]);
            mm = fmaxf(mm, __shfl_xor_sync(0xffffffffu, mm, 1));
            mm = fmaxf(mm, __shfl_xor_sync(0xffffffffu, mm, 2));
        }
        if ((tid & 3) == 0) {
            out_s[chl] = ss * (1.0f / 48.0f);
            out_m[chl] = mm;
        }
    }
    __syncthreads();
    if (tid < 64)        g_bmean [blk_ch + tid]      = out_s[tid];
    else if (tid < 128)  g_pooled[blk_ch + tid - 64] = out_m[tid - 64];
}

// ---------------------------------------------------------------------------
// GEMM1 split-K: hp[s] = pooled[512, k-chunk] @ W1[128, k-chunk]^T (unchanged)
// ---------------------------------------------------------------------------
__global__ void __launch_bounds__(256) gemm1(
    const float* __restrict__ A, const float* __restrict__ Bw,
    float* __restrict__ hp)
{
    __shared__ float As[16][68];
    __shared__ float Bs[16][68];
    int s  = blockIdx.z;
    int m0 = blockIdx.x * 64;
    int n0 = blockIdx.y * 64;
    int k0 = s * (Cc / S1);
    int tid = threadIdx.x;
    int tx = tid & 15, ty = tid >> 4;
    int r  = tid >> 2;
    int q  = (tid & 3) * 4;
    float acc[4][4] = {};

    const float* ap = &A [(size_t)(m0 + r) * Cc + k0 + q];
    const float* bp = &Bw[(size_t)(n0 + r) * Cc + k0 + q];
    float4 areg = *(const float4*)ap;
    float4 breg = *(const float4*)bp;

    #pragma unroll
    for (int kt = 0; kt < Cc / S1; kt += 16) {
        As[q+0][r] = areg.x; As[q+1][r] = areg.y; As[q+2][r] = areg.z; As[q+3][r] = areg.w;
        Bs[q+0][r] = breg.x; Bs[q+1][r] = breg.y; Bs[q+2][r] = breg.z; Bs[q+3][r] = breg.w;
        __syncthreads();
        if (kt + 16 < Cc / S1) {
            areg = *(const float4*)(ap + kt + 16);
            breg = *(const float4*)(bp + kt + 16);
        }
        #pragma unroll
        for (int kk = 0; kk < 16; kk++) {
            float4 a4 = *(const float4*)&As[kk][ty * 4];
            float4 b4 = *(const float4*)&Bs[kk][tx * 4];
            float a[4]  = {a4.x, a4.y, a4.z, a4.w};
            float bb[4] = {b4.x, b4.y, b4.z, b4.w};
            #pragma unroll
            for (int i = 0; i < 4; i++)
                #pragma unroll
                for (int j = 0; j < 4; j++)
                    acc[i][j] = fmaf(a[i], bb[j], acc[i][j]);
        }
        __syncthreads();
    }
    #pragma unroll
    for (int i = 0; i < 4; i++) {
        int m = m0 + ty * 4 + i;
        #pragma unroll
        for (int j = 0; j < 4; j++) {
            int n = n0 + tx * 4 + j;
            hp[((size_t)s * Bb + m) * HIDn + n] = acc[i][j];
        }
    }
}

// ---------------------------------------------------------------------------
// hreduce: h = relu(sum_s hp[s] + b1)  (unchanged)
// ---------------------------------------------------------------------------
__global__ void __launch_bounds__(256) hreduce(const float* __restrict__ b1v)
{
    int i4 = blockIdx.x * 256 + threadIdx.x;
    float4 v = *(const float4*)&g_hp[(size_t)i4 * 4];
    #pragma unroll
    for (int s = 1; s < S1; s++) {
        float4 t = *(const float4*)&g_hp[(size_t)s * (Bb * HIDn) + (size_t)i4 * 4];
        v.x += t.x; v.y += t.y; v.z += t.z; v.w += t.w;
    }
    float4 bv = *(const float4*)&b1v[(i4 & 31) * 4];
    v.x = fmaxf(v.x + bv.x, 0.f);
    v.y = fmaxf(v.y + bv.y, 0.f);
    v.z = fmaxf(v.z + bv.z, 0.f);
    v.w = fmaxf(v.w + bv.w, 0.f);
    *(float4*)&g_h[(size_t)i4 * 4] = v;
}

// ---------------------------------------------------------------------------
// GATE v4: 32(batch)x64(chan) tile, 128 threads, grid 512 (R5 skeleton),
// but ALL of K=128 staged in smem up front -> ONE barrier in the mainloop
// instead of 8. Pure LDS+FFMA after that, full ILP.
//   As[128][36] (k-major, 32 batch rows)  18.4 KB
//   Bs[128][68] (k-major, 64 chan cols)   34.8 KB   total 53 KB
// Epilogue identical to R5 (proven): gapT/WlT overlay As/Bs regions.
// ---------------------------------------------------------------------------
__global__ void __launch_bounds__(128) gemm_gate(
    const float* __restrict__ W2,  const float* __restrict__ b2v,
    const float* __restrict__ Wl,  const int*   __restrict__ pose)
{
    __shared__ __align__(16) float smemBuf[128 * 36 + 128 * 68];   // 53248 B
    float (*As)[36]   = (float(*)[36]) smemBuf;                    // [128][36]
    float (*Bs)[68]   = (float(*)[68])(smemBuf + 128 * 36);        // [128][68]
    float (*gapT)[36] = (float(*)[36]) smemBuf;                    // [64][36]
    float (*WlT)[68]  = (float(*)[68])(smemBuf + 128 * 36);        // [64][68]

    int m0 = blockIdx.x * 32;
    int n0 = blockIdx.y * 64;
    int tid = threadIdx.x;
    int tx = tid & 15, ty = tid >> 4;       // ty 0..7
    float acc[4][4] = {};

    // ---- load phase: entire K=128 for A (32 rows) and B (64 rows) ----
    {
        int ra = tid >> 2;                  // 0..31
        int qa = (tid & 3) * 4;             // 0,4,8,12
        const float* ap = &g_h[(size_t)(m0 + ra) * HIDn + qa];
        #pragma unroll
        for (int kc = 0; kc < HIDn; kc += 16) {
            float4 v = *(const float4*)(ap + kc);
            As[kc + qa + 0][ra] = v.x;
            As[kc + qa + 1][ra] = v.y;
            As[kc + qa + 2][ra] = v.z;
            As[kc + qa + 3][ra] = v.w;
        }
        int rb = tid >> 1;                  // 0..63
        int qb = (tid & 1) * 4;             // 0 or 4
        const float* bp = &W2[(size_t)(n0 + rb) * HIDn + qb];
        #pragma unroll
        for (int kc = 0; kc < HIDn; kc += 8) {
            float4 v = *(const float4*)(bp + kc);
            Bs[kc + qb + 0][rb] = v.x;
            Bs[kc + qb + 1][rb] = v.y;
            Bs[kc + qb + 2][rb] = v.z;
            Bs[kc + qb + 3][rb] = v.w;
        }
    }
    __syncthreads();

    // ---- compute: 128 kk iterations, zero barriers ----
    #pragma unroll 8
    for (int kk = 0; kk < HIDn; kk++) {
        float4 a4 = *(const float4*)&As[kk][ty * 4];
        float4 b4 = *(const float4*)&Bs[kk][tx * 4];
        float a[4]  = {a4.x, a4.y, a4.z, a4.w};
        float bb[4] = {b4.x, b4.y, b4.z, b4.w};
        #pragma unroll
        for (int i = 0; i < 4; i++)
            #pragma unroll
            for (int j = 0; j < 4; j++)
                acc[i][j] = fmaf(a[i], bb[j], acc[i][j]);
    }
    __syncthreads();    // smem free for epilogue overlay

    // ---- epilogue (R5-proven): gap -> gapT, Wl -> WlT, mini-GEMM -> zp ----
    #pragma unroll
    for (int i = 0; i < 4; i++) {
        int m = m0 + ty * 4 + i;
        float fr = (pose[m] == 1) ? 1.0f : 0.0f;
        #pragma unroll
        for (int j = 0; j < 4; j++) {
            int n = n0 + tx * 4 + j;
            float v = acc[i][j] + b2v[n];
            float g = 1.0f / (1.0f + expf(-v));
            gapT[tx * 4 + j][ty * 4 + i] =
                g_bmean[(size_t)m * Cc + n] + fr * g;
        }
    }
    for (int idx = tid; idx < 64 * 68; idx += 128) {
        int cc = idx / 68, j = idx - cc * 68;
        WlT[cc][j] = (j < NAT) ? Wl[(size_t)j * Cc + n0 + cc] : 0.f;
    }
    __syncthreads();

    float acc2[4][4] = {};
    #pragma unroll 8
    for (int cc = 0; cc < 64; cc++) {
        float4 g4 = *(const float4*)&gapT[cc][ty * 4];
        float4 w4 = *(const float4*)&WlT [cc][tx * 4];
        float gg[4] = {g4.x, g4.y, g4.z, g4.w};
        float ww[4] = {w4.x, w4.y, w4.z, w4.w};
        #pragma unroll
        for (int i = 0; i < 4; i++)
            #pragma unroll
            for (int j = 0; j < 4; j++)
                acc2[i][j] = fmaf(gg[i], ww[j], acc2[i][j]);
    }
    int nt = blockIdx.y;
    #pragma unroll
    for (int j = 0; j < 4; j++) {
        int attr = tx * 4 + j;
        if (attr < NAT) {
            #pragma unroll
            for (int i = 0; i < 4; i++) {
                int m = m0 + ty * 4 + i;
                g_zp[((size_t)nt * NAT + attr) * Bb + m] = acc2[i][j];
            }
        }
    }
}

// ---------------------------------------------------------------------------
// BN: one block per attribute (NTIL=32 partials).
// ---------------------------------------------------------------------------
__global__ void __launch_bounds__(256) bn_kernel(
    const float* __restrict__ blv, const float* __restrict__ gam,
    const float* __restrict__ bet, float* __restrict__ out)
{
    __shared__ float zbuf[Bb];
    __shared__ float red[256];
    int j   = blockIdx.x;
    int tid = threadIdx.x;
    float bias = blv[j];
    float lsum = 0.f;
    for (int b = tid; b < Bb; b += 256) {
        float z = bias;
        #pragma unroll
        for (int nt = 0; nt < NTIL; nt++)
            z += g_zp[((size_t)nt * NAT + j) * Bb + b];
        zbuf[b] = z;
        lsum += z;
    }
    red[tid] = lsum;
    __syncthreads();
    for (int off = 128; off; off >>= 1) {
        if (tid < off) red[tid] += red[tid + off];
        __syncthreads();
    }
    float mu = red[0] * (1.0f / Bb);
    __syncthreads();
    float lvar = 0.f;
    for (int b = tid; b < Bb; b += 256) {
        float d = zbuf[b] - mu;
        lvar += d * d;
    }
    red[tid] = lvar;
    __syncthreads();
    for (int off = 128; off; off >>= 1) {
        if (tid < off) red[tid] += red[tid + off];
        __syncthreads();
    }
    float inv = rsqrtf(red[0] * (1.0f / Bb) + 1e-5f);
    float ga = gam[j], be = bet[j];
    for (int b = tid; b < Bb; b += 256)
        out[(size_t)b * NAT + j] = ga * (zbuf[b] - mu) * inv + be;
}

// ---------------------------------------------------------------------------
extern "C" void kernel_launch(void* const* d_in, const int* in_sizes, int n_in,
                              void* d_out, int out_size)
{
    const float* body = (const float*)d_in[0];
    const float* face = (const float*)d_in[1];
    const int*   pose = (const int*)  d_in[2];
    const float* Af   = (const float*)d_in[3];
    const float* W1   = (const float*)d_in[4];
    const float* b1v  = (const float*)d_in[5];
    const float* W2   = (const float*)d_in[6];
    const float* b2v  = (const float*)d_in[7];
    const float* Wl   = (const float*)d_in[8];
    const float* blv  = (const float*)d_in[9];
    const float* gam  = (const float*)d_in[10];
    const float* bet  = (const float*)d_in[11];
    float* out = (float*)d_out;

    float *pooled_p, *hp_p;
    cudaGetSymbolAddress((void**)&pooled_p, g_pooled);
    cudaGetSymbolAddress((void**)&hp_p,     g_hp);

    // 1) streaming reduce: pooled max + body mean
    k1_reduce<<<(Bb * Cc) / 64, 256>>>(body, face, Af, pose);
    // 2) hp[s] = pooled @ W1^T  (16-way split-K partials)
    gemm1<<<dim3(Bb / 64, HIDn / 64, S1), 256>>>(pooled_p, W1, hp_p);
    // 3) h = relu(sum hp + b1)
    hreduce<<<(Bb * HIDn / 4) / 256, 256>>>(b1v);
    // 4) gate GEMM v4 (full-K smem, 1 barrier) + fused z-partials
    gemm_gate<<<dim3(Bb / 32, NTIL), 128>>>(W2, b2v, Wl, pose);
    // 5) reduce partials + bias + batchnorm
    bn_kernel<<<NAT, 256>>>(blv, gam, bet, out);
}